// round 17
// baseline (speedup 1.0000x reference)
#include <cuda_runtime.h>

#define POOL 7
#define NUM_ROIS 300
#define IMG_H 200
#define IMG_W 200
#define IMG_C 512

#define CP16(dst_u32, src) \
    asm volatile("cp.async.cg.shared.global [%0], [%1], 16;" :: "r"(dst_u32), "l"(src))
#define CP_COMMIT() asm volatile("cp.async.commit_group;")
#define CP_WAIT(N)  asm volatile("cp.async.wait_group %0;" :: "n"(N))

__device__ __forceinline__ unsigned su32(const void* p) {
    return (unsigned)__cvta_generic_to_shared(p);
}

__device__ __forceinline__ float4 lerp4(float4 a, float4 b, float ga, float fb)
{
    float4 r;
    r.x = a.x * ga + b.x * fb;
    r.y = a.y * ga + b.y * fb;
    r.z = a.z * ga + b.z * fb;
    r.w = a.w * ga + b.w * fb;
    return r;
}

struct HCoord { int e0, e1; float fx; bool needX; };

__device__ __forceinline__ HCoord hcoord(int px, float sx, int w, int x0)
{
    HCoord hc;
    const float xs = (float)px * sx;
    int ix0 = (int)floorf(xs);
    hc.fx = xs - (float)ix0;            // frac BEFORE clamp (matches ref)
    ix0 = min(ix0, w - 1);
    const int ix1 = min(ix0 + 1, w - 1);
    hc.needX = (hc.fx != 0.0f) && (ix1 != ix0);
    hc.e0 = (x0 + ix0) * IMG_C;
    hc.e1 = (x0 + ix1) * IMG_C;
    return hc;
}

// CTA = (roi, py): all 7 px positions. 128 threads, 4 channels each.
// Every needed corner load for the CTA goes out as cp.async in ONE commit
// group (register-free depth up to 28 copies/thread), single wait, then
// compute + store all 7 outputs. Thread-private slots -> no __syncthreads.
// 56 KB dynamic SMEM -> 4 CTAs/SM; per-SM in-flight reads ~170 KB, which
// saturates the LTS service rate independent of warp occupancy.
__global__ __launch_bounds__(128) void roi_pool_kernel(
    const float* __restrict__ img,   // [H, W, C]
    const float* __restrict__ rois,  // [NUM_ROIS, 4] (x, y, w, h) as float
    float* __restrict__ out)         // [NUM_ROIS, POOL, POOL, C]
{
    extern __shared__ float4 sbuf[];       // [7 px][4 corners][128 tid] = 56 KB

    const int rp   = blockIdx.x;           // roi*7 + py, 0..2099
    const int roi  = rp / POOL;
    const int py   = rp - roi * POOL;
    const int t    = threadIdx.x;
    const int c    = t * 4;

    // ---- ROI geometry (uniform across block) ----
    const int rx = (int)__ldg(&rois[roi * 4 + 0]);
    const int ry = (int)__ldg(&rois[roi * 4 + 1]);
    const int rw = (int)__ldg(&rois[roi * 4 + 2]);
    const int rh = (int)__ldg(&rois[roi * 4 + 3]);

    const int x0 = min(max(rx, 0), IMG_W - 1);
    const int y0 = min(max(ry, 0), IMG_H - 1);
    const int w  = min(max(rw, 1), IMG_W - x0);
    const int h  = min(max(rh, 1), IMG_H - y0);

    // TF1 resize (align_corners=False): src = dst * (in/out); exact fp32 div
    const float sx = (float)w / (float)POOL;
    const float sy = (float)h / (float)POOL;

    // ---- vertical coords (fixed for this block) ----
    const float ys = (float)py * sy;
    int iy0 = (int)floorf(ys);
    const float fy = ys - (float)iy0;      // frac BEFORE clamp
    iy0 = min(iy0, h - 1);
    const int iy1 = min(iy0 + 1, h - 1);
    const bool needY = (fy != 0.0f) && (iy1 != iy0);

    const float* __restrict__ row0 = img + (long)((y0 + iy0) * IMG_W) * IMG_C + c;
    const float* __restrict__ row1 = img + (long)((y0 + iy1) * IMG_W) * IMG_C + c;
    float* __restrict__ obase = out + (long)rp * (POOL * IMG_C) + c;

    // ---- horizontal coords for all 7 px ----
    HCoord hc[POOL];
    #pragma unroll
    for (int px = 0; px < POOL; ++px) hc[px] = hcoord(px, sx, w, x0);

    // ---- issue ALL loads, one commit group (coarsest batching) ----
    #pragma unroll
    for (int px = 0; px < POOL; ++px) {
        float4* pb = &sbuf[(px * 4) * 128];      // [corner][tid]
        CP16(su32(pb + 0 * 128 + t), row0 + hc[px].e0);
        if (hc[px].needX) CP16(su32(pb + 1 * 128 + t), row0 + hc[px].e1);
        if (needY) {
            CP16(su32(pb + 2 * 128 + t), row1 + hc[px].e0);
            if (hc[px].needX) CP16(su32(pb + 3 * 128 + t), row1 + hc[px].e1);
        }
    }
    CP_COMMIT();
    CP_WAIT(0);

    // ---- compute + store all 7 outputs ----
    const float gy = 1.0f - fy;
    #pragma unroll
    for (int px = 0; px < POOL; ++px) {
        const float4* pb = &sbuf[(px * 4) * 128];
        const float gx = 1.0f - hc[px].fx;

        const float4 v00 = pb[0 * 128 + t];
        float4 top = hc[px].needX ? lerp4(v00, pb[1 * 128 + t], gx, hc[px].fx) : v00;
        float4 r;
        if (needY) {
            const float4 v10 = pb[2 * 128 + t];
            const float4 bot = hc[px].needX ? lerp4(v10, pb[3 * 128 + t], gx, hc[px].fx) : v10;
            r = lerp4(top, bot, gy, fy);
        } else {
            r = top;
        }
        __stcs((float4*)(obase + px * IMG_C), r);
    }
}

extern "C" void kernel_launch(void* const* d_in, const int* in_sizes, int n_in,
                              void* d_out, int out_size)
{
    const float* img  = (const float*)d_in[0];
    const float* rois = (const float*)d_in[1];
    float* out = (float*)d_out;

    const int smem = POOL * 4 * 128 * (int)sizeof(float4);   // 57344 B
    cudaFuncSetAttribute(roi_pool_kernel,
                         cudaFuncAttributeMaxDynamicSharedMemorySize, smem);

    const int nblocks = NUM_ROIS * POOL;  // 2100
    roi_pool_kernel<<<nblocks, 128, smem>>>(img, rois, out);
}